// round 17
// baseline (speedup 1.0000x reference)
#include <cuda_runtime.h>
#include <cuda_bf16.h>
#include <cstdint>

#define T_LEN 512
#define B_SZ  256
#define I_SZ  128
#define H_SZ  256
#define G_SZ  768
#define L_NUM 6

#define M_ROWS (T_LEN * B_SZ)                  // 131072
#define TBH    ((size_t)T_LEN * B_SZ * H_SZ)   // 33554432
#define BH     (B_SZ * H_SZ)                   // 65536

typedef unsigned long long ull;

// ------------------------------ scratch -----------------------------------
__device__ __nv_bfloat16 g_xhi[(size_t)M_ROWS * I_SZ];   // layer-0 input split
__device__ __nv_bfloat16 g_xlo[(size_t)M_ROWS * I_SZ];
__device__ __nv_bfloat16 g_ahi[(size_t)M_ROWS * H_SZ];   // inter-layer h split
__device__ __nv_bfloat16 g_alo[(size_t)M_ROWS * H_SZ];
__device__ __nv_bfloat16 g_hex[2][B_SZ][512];            // [parity][row][hi|lo]
__device__ __align__(128) ull g_bar2[16][16];

// ------------------------------ helpers -----------------------------------
__device__ __forceinline__ float tanh_f(float x) {
    float y; asm("tanh.approx.f32 %0, %1;" : "=f"(y) : "f"(x)); return y;
}
__device__ __forceinline__ float sigmf(float x) {
    return 0.5f * tanh_f(0.5f * x) + 0.5f;
}
__device__ __forceinline__ uint32_t smem_u32(const void* p) {
    uint32_t a;
    asm("{ .reg .u64 t; cvta.to.shared.u64 t, %1; cvt.u32.u64 %0, t; }"
        : "=r"(a) : "l"(p));
    return a;
}

// ------------------------- fp32 -> bf16 hi/lo split -------------------------
__device__ __forceinline__ uint32_t bpack(float a, float b, bool lo) {
    __nv_bfloat16 ah = __float2bfloat16(a);
    __nv_bfloat16 bh = __float2bfloat16(b);
    if (lo) {
        ah = __float2bfloat16(a - __bfloat162float(ah));
        bh = __float2bfloat16(b - __bfloat162float(bh));
    }
    return (uint32_t)__bfloat16_as_ushort(ah) |
           ((uint32_t)__bfloat16_as_ushort(bh) << 16);
}

// split x (layer-0 input) into g_xhi/g_xlo
__global__ void conv_kernel(const float* __restrict__ A, int n4)
{
    int i = blockIdx.x * 256 + threadIdx.x;
    if (i < n4) {
        float4 v = ((const float4*)A)[i];
        ((uint2*)g_xhi)[i] = make_uint2(bpack(v.x, v.y, false), bpack(v.z, v.w, false));
        ((uint2*)g_xlo)[i] = make_uint2(bpack(v.x, v.y, true),  bpack(v.z, v.w, true));
    }
}

// ------------------------ mma primitives (proven) ---------------------------
__device__ __forceinline__ void ldmx4(uint32_t* r, uint32_t addr) {
    asm volatile("ldmatrix.sync.aligned.m8n8.x4.shared.b16 {%0,%1,%2,%3}, [%4];"
                 : "=r"(r[0]), "=r"(r[1]), "=r"(r[2]), "=r"(r[3]) : "r"(addr));
}
__device__ __forceinline__ void ldmx2(uint32_t* r, uint32_t addr) {
    asm volatile("ldmatrix.sync.aligned.m8n8.x2.shared.b16 {%0,%1}, [%2];"
                 : "=r"(r[0]), "=r"(r[1]) : "r"(addr));
}
__device__ __forceinline__ void mma16816(float* d, const uint32_t* a,
                                         uint32_t b0, uint32_t b1) {
    asm volatile(
        "mma.sync.aligned.m16n8k16.row.col.f32.bf16.bf16.f32 "
        "{%0,%1,%2,%3}, {%4,%5,%6,%7}, {%8,%9}, {%0,%1,%2,%3};"
        : "+f"(d[0]), "+f"(d[1]), "+f"(d[2]), "+f"(d[3])
        : "r"(a[0]), "r"(a[1]), "r"(a[2]), "r"(a[3]), "r"(b0), "r"(b1));
}
__device__ __forceinline__ void cpasync16(uint32_t saddr, const void* g) {
    asm volatile("cp.async.ca.shared.global [%0], [%1], 16;"
                 :: "r"(saddr), "l"(g) : "memory");
}

// ---------------------------------------------------------------------------
// Fully fused persistent GRU layer, v2: ih projection for t+1 computed in
// the barrier shadow (release-arrive early, acquire-poll late).
// ---------------------------------------------------------------------------
#define SROW  264
#define SROWB (SROW * 2)
#define AS_E  (16 * SROW)
#define WREG_B 101376
#define SCAN_SMEM 160256

template<int KI>
__global__ void __launch_bounds__(256)
gru_scan_kernel(const float* __restrict__ Whh, const float* __restrict__ Wih,
                const float* __restrict__ bhh, const float* __restrict__ bih,
                const __nv_bfloat16* __restrict__ Ainh,
                const __nv_bfloat16* __restrict__ Ainl,
                const float* __restrict__ hinit,
                float* __restrict__ out, float* __restrict__ finals, int wnext)
{
    constexpr int SROWI = KI + 8;
    constexpr int WI_E  = 96 * SROWI;
    constexpr int AI_E  = 16 * SROWI;
    constexpr int AIBUF = 2 * AI_E * 2;
    constexpr int KIH   = KI / 32;
    constexpr int CH    = 16 * KI / 8;

    extern __shared__ char sm[];
    __nv_bfloat16* Wsm = (__nv_bfloat16*)sm;
    __nv_bfloat16* ASH = (__nv_bfloat16*)(sm + WREG_B);
    __nv_bfloat16* ASL = ASH + AS_E;
    char* AIbase = sm + WREG_B + 2 * AS_E * 2;
    float* red = (float*)(sm + WREG_B + 2 * AS_E * 2 + 2 * (2 * (16*264) * 2));

    const int tid = threadIdx.x;
    const int bg = blockIdx.x >> 3;
    const int hg = blockIdx.x & 7;
    const int b0 = bg * 16;
    const int h0 = hg * 32;

    const int wid  = tid >> 5;
    const int L    = tid & 31;
    const int wmod = wid & 3;
    const int ks   = wid >> 2;
    const int gr   = L >> 2;
    const int ch   = h0 + wmod * 8 + (L & 3) * 2;
    const int tl   = tid & 127;

    __shared__ ull s_tok;   // barrier token shared between arrive and poll

    // ---- prologue 1: split W_hh, hoist fragments ----
    {
        __nv_bfloat16* WhH = Wsm;
        __nv_bfloat16* WhL = Wsm + 96 * SROW;
        for (int idx = tid; idx < 96 * 256; idx += 256) {
            int j = idx >> 8;
            int k = idx & 255;
            float v = Whh[(size_t)((j >> 5) * 256 + h0 + (j & 31)) * 256 + k];
            __nv_bfloat16 hb = __float2bfloat16(v);
            WhH[j * SROW + k] = hb;
            WhL[j * SROW + k] = __float2bfloat16(v - __bfloat162float(hb));
        }
    }
    __syncthreads();

    uint32_t Bf0[3][8][2], Bf1[3][8][2];
    {
        const uint32_t bHb = smem_u32(Wsm) +
            (uint32_t)((L & 7) * SROWB + ((L >> 3) & 1) * 16);
        const uint32_t bLb = bHb + (uint32_t)(96 * SROW * 2);
        #pragma unroll
        for (int q = 0; q < 3; ++q) {
            const uint32_t nofs = (uint32_t)((wmod + q * 4) * 8 * SROWB);
            #pragma unroll
            for (int kk = 0; kk < 8; ++kk) {
                ldmx2(Bf0[q][kk], bHb + nofs + (ks * 8 + kk) * 32);
                ldmx2(Bf1[q][kk], bLb + nofs + (ks * 8 + kk) * 32);
            }
        }
    }
    __syncthreads();

    // ---- prologue 2: split W_ih; stage A(0); stage h(0) ----
    for (int idx = tid; idx < 96 * KI; idx += 256) {
        int j = idx / KI;
        int k = idx % KI;
        float v = Wih[(size_t)((j >> 5) * 256 + h0 + (j & 31)) * KI + k];
        __nv_bfloat16 hb = __float2bfloat16(v);
        Wsm[j * SROWI + k] = hb;
        (Wsm + WI_E)[j * SROWI + k] = __float2bfloat16(v - __bfloat162float(hb));
    }
    for (int f = tid; f < 2 * CH; f += 256) {
        int which = (f >= CH) ? 1 : 0;
        int g = f - which * CH;
        int row = g / (KI / 8);
        int q = g % (KI / 8);
        const __nv_bfloat16* src = (which ? Ainl : Ainh) +
            (size_t)(b0 + row) * KI + q * 8;
        *(uint4*)(AIbase + which * (AI_E * 2) + row * (SROWI * 2) + q * 16) =
            *(const uint4*)src;
    }
    {
        const float4* src4 = (const float4*)(hinit + (size_t)b0 * 256);
        #pragma unroll
        for (int p = 0; p < 4; ++p) {
            int f = tid + p * 256;
            int row = f >> 6;
            int kq = f & 63;
            float4 v = src4[row * 64 + kq];
            uint2 hiw, low;
            hiw.x = bpack(v.x, v.y, false); hiw.y = bpack(v.z, v.w, false);
            low.x = bpack(v.x, v.y, true);  low.y = bpack(v.z, v.w, true);
            *(uint2*)(ASH + row * SROW + kq * 4) = hiw;
            *(uint2*)(ASL + row * SROW + kq * 4) = low;
        }
    }

    float2 br, bz, bni, bnh, hp0, hp1;
    if (ks == 0) {
        br.x = bih[ch]     + bhh[ch];
        br.y = bih[ch + 1] + bhh[ch + 1];
        bz.x = bih[256 + ch]     + bhh[256 + ch];
        bz.y = bih[256 + ch + 1] + bhh[256 + ch + 1];
        bni  = *(const float2*)(bih + 512 + ch);
        bnh  = *(const float2*)(bhh + 512 + ch);
        hp0 = *(const float2*)(hinit + (size_t)(b0 + gr) * 256 + ch);
        hp1 = *(const float2*)(hinit + (size_t)(b0 + gr + 8) * 256 + ch);
    }
    __syncthreads();

    const uint32_t aH = smem_u32(ASH) +
        (uint32_t)((L & 15) * SROWB + (L >> 4) * 16);
    const uint32_t aL = aH + (uint32_t)(AS_E * 2);
    const uint32_t iB = smem_u32(AIbase) +
        (uint32_t)((L & 15) * (SROWI * 2) + (L >> 4) * 16);
    const uint32_t wHb = smem_u32(Wsm) +
        (uint32_t)((L & 7) * (SROWI * 2) + ((L >> 3) & 1) * 16);
    const uint32_t wLb = wHb + (uint32_t)(WI_E * 2);
    const uint32_t aidst = smem_u32(AIbase);

    // ---- prologue 3: ih(0); prefetch A(1) ----
    float ihR[4] = {0,0,0,0}, ihZ[4] = {0,0,0,0}, ihN[4] = {0,0,0,0};
    #pragma unroll
    for (int kk = 0; kk < KIH; ++kk) {
        const uint32_t kxo = (uint32_t)((ks * KIH + kk) * 32);
        uint32_t ah[4], al[4];
        ldmx4(ah, iB + kxo);
        ldmx4(al, iB + AI_E * 2 + kxo);
        #pragma unroll
        for (int q = 0; q < 3; ++q) {
            uint32_t wh[2], wl[2];
            uint32_t no = (uint32_t)((wmod + q * 4) * 8 * (SROWI * 2)) + kxo;
            ldmx2(wh, wHb + no);
            ldmx2(wl, wLb + no);
            float* ac = (q == 0) ? ihR : (q == 1) ? ihZ : ihN;
            mma16816(ac, ah, wh[0], wh[1]);
            mma16816(ac, ah, wl[0], wl[1]);
            mma16816(ac, al, wh[0], wh[1]);
        }
    }
    {
        for (int f = tid; f < 2 * CH; f += 256) {
            int which = (f >= CH) ? 1 : 0;
            int g = f - which * CH;
            int row = g / (KI / 8);
            int q = g % (KI / 8);
            const __nv_bfloat16* src = (which ? Ainl : Ainh) +
                (size_t)(B_SZ + b0 + row) * KI + q * 8;
            cpasync16(aidst + AIBUF + which * (AI_E * 2)
                      + (uint32_t)(row * (SROWI * 2) + q * 16), src);
        }
        asm volatile("cp.async.commit_group;" ::: "memory");
    }

    for (int t = 0; t < T_LEN; ++t) {
        if (t > 0) {
            const uint4* src = (const uint4*)(&g_hex[t & 1][b0][0]);
            #pragma unroll
            for (int p = 0; p < 4; ++p) {
                int f = tid + p * 256;
                int row = f >> 6;
                int q = f & 63;
                uint4 v = __ldcv(src + row * 64 + q);
                __nv_bfloat16* dst = (q < 32)
                    ? (ASH + row * SROW + q * 8)
                    : (ASL + row * SROW + (q - 32) * 8);
                *(uint4*)dst = v;
            }
            __syncthreads();
        }

        float aR[4], aZ[4], aNi[4], aNh[4] = {0,0,0,0};
        #pragma unroll
        for (int i = 0; i < 4; ++i) { aR[i] = ihR[i]; aZ[i] = ihZ[i]; aNi[i] = ihN[i]; }

        #pragma unroll
        for (int kk = 0; kk < 8; ++kk) {
            const uint32_t kxo = (uint32_t)((ks * 8 + kk) * 32);
            uint32_t ah[4], al[4];
            ldmx4(ah, aH + kxo);
            ldmx4(al, aL + kxo);
            #pragma unroll
            for (int q = 0; q < 3; ++q) {
                float* ac = (q == 0) ? aR : (q == 1) ? aZ : aNh;
                mma16816(ac, ah, Bf0[q][kk][0], Bf0[q][kk][1]);
                mma16816(ac, ah, Bf1[q][kk][0], Bf1[q][kk][1]);
                mma16816(ac, al, Bf0[q][kk][0], Bf0[q][kk][1]);
            }
        }

        if (ks == 1) {
            float* rp = red + tl * 16;
            #pragma unroll
            for (int i = 0; i < 4; ++i) {
                rp[i] = aR[i]; rp[4 + i] = aZ[i];
                rp[8 + i] = aNi[i]; rp[12 + i] = aNh[i];
            }
        }
        __syncthreads();

        if (ks == 0) {
            const float* rp = red + tl * 16;
            #pragma unroll
            for (int i = 0; i < 4; ++i) {
                aR[i] += rp[i]; aZ[i] += rp[4 + i];
                aNi[i] += rp[8 + i]; aNh[i] += rp[12 + i];
            }

            float rg0 = sigmf(aR[0] + br.x);
            float rg1 = sigmf(aR[1] + br.y);
            float zg0 = sigmf(aZ[0] + bz.x);
            float zg1 = sigmf(aZ[1] + bz.y);
            float ng0 = tanh_f(aNi[0] + bni.x + rg0 * (aNh[0] + bnh.x));
            float ng1 = tanh_f(aNi[1] + bni.y + rg1 * (aNh[1] + bnh.y));
            float2 hv0 = { (1.0f - zg0) * ng0 + zg0 * hp0.x,
                           (1.0f - zg1) * ng1 + zg1 * hp0.y };
            float rg2 = sigmf(aR[2] + br.x);
            float rg3 = sigmf(aR[3] + br.y);
            float zg2 = sigmf(aZ[2] + bz.x);
            float zg3 = sigmf(aZ[3] + bz.y);
            float ng2 = tanh_f(aNi[2] + bni.x + rg2 * (aNh[2] + bnh.x));
            float ng3 = tanh_f(aNi[3] + bni.y + rg3 * (aNh[3] + bnh.y));
            float2 hv1 = { (1.0f - zg2) * ng2 + zg2 * hp1.x,
                           (1.0f - zg3) * ng3 + zg3 * hp1.y };

            hp0 = hv0; hp1 = hv1;

            const size_t r0 = (size_t)t * B_SZ + b0 + gr;
            const size_t r1 = r0 + 8;
            uint32_t w0h = bpack(hv0.x, hv0.y, false);
            uint32_t w0l = bpack(hv0.x, hv0.y, true);
            uint32_t w1h = bpack(hv1.x, hv1.y, false);
            uint32_t w1l = bpack(hv1.x, hv1.y, true);

            if (wnext) {
                *(uint32_t*)(g_ahi + r0 * 256 + ch) = w0h;
                *(uint32_t*)(g_alo + r0 * 256 + ch) = w0l;
                *(uint32_t*)(g_ahi + r1 * 256 + ch) = w1h;
                *(uint32_t*)(g_alo + r1 * 256 + ch) = w1l;
            } else {
                *(float2*)(out + r0 * 256 + ch) = hv0;
                *(float2*)(out + r1 * 256 + ch) = hv1;
            }

            if (t == T_LEN - 1) {
                *(float2*)(finals + (size_t)(b0 + gr) * 256 + ch) = hv0;
                *(float2*)(finals + (size_t)(b0 + gr + 8) * 256 + ch) = hv1;
            } else {
                int par = (t + 1) & 1;
                __nv_bfloat16* e0 = &g_hex[par][b0 + gr][0];
                __nv_bfloat16* e1 = &g_hex[par][b0 + gr + 8][0];
                *(uint32_t*)(e0 + ch)       = w0h;
                *(uint32_t*)(e0 + 256 + ch) = w0l;
                *(uint32_t*)(e1 + ch)       = w1h;
                *(uint32_t*)(e1 + 256 + ch) = w1l;
            }
        }

        if (t == T_LEN - 1) break;

        // ---- split barrier: arrive, then ih(t+1) in the wait shadow ----
        __syncthreads();                      // exchange writes CTA-complete
        if (tid == 0) {
            ull old;
            asm volatile("atom.release.gpu.global.add.u64 %0, [%1], 1;"
                         : "=l"(old) : "l"(&g_bar2[bg][0]) : "memory");
            s_tok = ((old + 1ULL + 7ULL) >> 3) << 3;   // round up to mult of 8
        }
        asm volatile("cp.async.wait_group 0;" ::: "memory");
        __syncthreads();                      // A(t+1) smem visible + s_tok set

        {   // ih(t+1) from buffer (t+1)&1  — runs while peers catch up
            const uint32_t ib = iB + (uint32_t)(((t + 1) & 1) * AIBUF);
            #pragma unroll
            for (int i = 0; i < 4; ++i) { ihR[i] = 0; ihZ[i] = 0; ihN[i] = 0; }
            #pragma unroll
            for (int kk = 0; kk < KIH; ++kk) {
                const uint32_t kxo = (uint32_t)((ks * KIH + kk) * 32);
                uint32_t ah[4], al[4];
                ldmx4(ah, ib + kxo);
                ldmx4(al, ib + AI_E * 2 + kxo);
                #pragma unroll
                for (int q = 0; q < 3; ++q) {
                    uint32_t wh[2], wl[2];
                    uint32_t no = (uint32_t)((wmod + q * 4) * 8 * (SROWI * 2)) + kxo;
                    ldmx2(wh, wHb + no);
                    ldmx2(wl, wLb + no);
                    float* ac = (q == 0) ? ihR : (q == 1) ? ihZ : ihN;
                    mma16816(ac, ah, wh[0], wh[1]);
                    mma16816(ac, ah, wl[0], wl[1]);
                    mma16816(ac, al, wh[0], wh[1]);
                }
            }
        }
        if (t + 2 < T_LEN) {   // prefetch A(t+2) into buffer t&1
            uint32_t db = aidst + (uint32_t)((t & 1) * AIBUF);
            for (int f = tid; f < 2 * CH; f += 256) {
                int which = (f >= CH) ? 1 : 0;
                int g = f - which * CH;
                int row = g / (KI / 8);
                int q = g % (KI / 8);
                const __nv_bfloat16* src = (which ? Ainl : Ainh) +
                    (size_t)((t + 2) * B_SZ + b0 + row) * KI + q * 8;
                cpasync16(db + which * (AI_E * 2)
                          + (uint32_t)(row * (SROWI * 2) + q * 16), src);
            }
            asm volatile("cp.async.commit_group;" ::: "memory");
        }

        if (tid == 0) {   // acquire poll against the stored token
            ull* ctr = &g_bar2[bg][0];
            ull target = s_tok;
            ull v;
            do {
                asm volatile("ld.acquire.gpu.global.u64 %0, [%1];"
                             : "=l"(v) : "l"(ctr) : "memory");
            } while (v < target);
        }
        __syncthreads();
    }
}

// ---------------------------------------------------------------------------
extern "C" void kernel_launch(void* const* d_in, const int* in_sizes, int n_in,
                              void* d_out, int out_size)
{
    const float* x     = (const float*)d_in[0];
    const float* h0    = (const float*)d_in[1];
    const float* Wih0  = (const float*)d_in[2];
    const float* Wih   = (const float*)d_in[3];
    const float* Whh   = (const float*)d_in[4];
    const float* bih   = (const float*)d_in[5];
    const float* bhh   = (const float*)d_in[6];
    float* out = (float*)d_out;

    __nv_bfloat16 *xhi_p, *xlo_p, *ahi_p, *alo_p;
    cudaGetSymbolAddress((void**)&xhi_p, g_xhi);
    cudaGetSymbolAddress((void**)&xlo_p, g_xlo);
    cudaGetSymbolAddress((void**)&ahi_p, g_ahi);
    cudaGetSymbolAddress((void**)&alo_p, g_alo);

    cudaFuncSetAttribute(gru_scan_kernel<128>,
                         cudaFuncAttributeMaxDynamicSharedMemorySize, SCAN_SMEM);
    cudaFuncSetAttribute(gru_scan_kernel<256>,
                         cudaFuncAttributeMaxDynamicSharedMemorySize, SCAN_SMEM);

    int n4 = M_ROWS * I_SZ / 4;
    conv_kernel<<<(n4 + 255) / 256, 256>>>(x, n4);

    for (int l = 0; l < L_NUM; ++l) {
        const float* Wi  = (l == 0) ? Wih0 : Wih + (size_t)(l - 1) * G_SZ * H_SZ;
        const float* Wh  = Whh + (size_t)l * G_SZ * H_SZ;
        const float* bi  = bih + (size_t)l * G_SZ;
        const float* bh  = bhh + (size_t)l * G_SZ;
        float* fin = out + TBH + (size_t)l * BH;
        int wnext = (l < L_NUM - 1) ? 1 : 0;

        if (l == 0) {
            gru_scan_kernel<128><<<128, 256, SCAN_SMEM>>>(
                Wh, Wi, bh, bi, xhi_p, xlo_p,
                h0 + (size_t)l * BH, out, fin, wnext);
        } else {
            gru_scan_kernel<256><<<128, 256, SCAN_SMEM>>>(
                Wh, Wi, bh, bi, ahi_p, alo_p,
                h0 + (size_t)l * BH, out, fin, wnext);
        }
    }
}